// round 1
// baseline (speedup 1.0000x reference)
#include <cuda_runtime.h>
#include <cstdint>

// ============================================================================
// MonteCarloNet: out[m,n] = sum_g Wf[g] * tanh(2*mask2[m,n,g] *
//                  sum_f (mask1[m,n,f]*tanh(2*in[n]*W1[f])) * W2[g,f])
// Masks are bit-exact JAX threefry2x32 bernoulli(0.5) draws, seed key(42),
// split into km1 (mask1) and km2 (mask2).
//
// RNG mode switches (flip these if rel_err comes back O(1)):
//   JAX_PARTITIONABLE=1 : jax_threefry_partitionable (default True, JAX>=0.4.30)
//       split  : km_i  = threefry_block(key, x0=0, x1=i)   (fold_in of iota)
//       bits_i : block(km, x0=0, x1=i) -> out0 ^ out1      (PART_XOR=1)
//   JAX_PARTITIONABLE=0 : original mode
//       split  : counts [0,1,2,3] -> blocks (0,2),(1,3); km1=(A.o0,B.o0), km2=(A.o1,B.o1)
//       bits_i : i<H: block(i,i+H).o0 ; else block(i-H,i).o1,  H = total/2
// bernoulli keep  <=>  bits < 2^31  (u = bitcast(bits>>9 | 0x3f800000)-1 < 0.5)
// ============================================================================

#define JAX_PARTITIONABLE 1
#define PART_XOR 1

#define NMC   1024
#define SEQ   2048
#define NF    64
#define TB    128            // threads per block (over n)
#define MPB   8              // m samples per block
#define MASK_TOTAL (NMC * SEQ * NF)       // 2^27
#define MASK_HALF  (MASK_TOTAL / 2)       // 2^26

struct KP { unsigned a, b; };

__host__ __device__ constexpr unsigned rotl32c(unsigned x, int d) {
  return (x << d) | (x >> (32 - d));
}

// Reference threefry2x32 block (constexpr-evaluable for the key schedule).
__host__ __device__ constexpr KP tf_block_c(unsigned k0, unsigned k1,
                                            unsigned x0, unsigned x1) {
  unsigned ks[3] = {k0, k1, k0 ^ k1 ^ 0x1BD11BDAu};
  int rot[2][4] = {{13, 15, 26, 6}, {17, 29, 16, 24}};
  x0 += ks[0]; x1 += ks[1];
  for (int g = 0; g < 5; ++g) {
    for (int j = 0; j < 4; ++j) {
      x0 += x1;
      x1 = rotl32c(x1, rot[g & 1][j]);
      x1 ^= x0;
    }
    x0 += ks[(g + 1) % 3];
    x1 += ks[(g + 2) % 3] + (unsigned)(g + 1);
  }
  return {x0, x1};
}

// jax.random.key(42) -> raw key (0, 42); derive km1, km2 at compile time.
#if JAX_PARTITIONABLE
constexpr KP KM1 = tf_block_c(0u, 42u, 0u, 0u);
constexpr KP KM2 = tf_block_c(0u, 42u, 0u, 1u);
#else
constexpr KP SPA = tf_block_c(0u, 42u, 0u, 2u);
constexpr KP SPB = tf_block_c(0u, 42u, 1u, 3u);
constexpr KP KM1 = {SPA.a, SPB.a};
constexpr KP KM2 = {SPA.b, SPB.b};
#endif

// Fast device block: keys are immediates, rotates are single SHF (funnel shift).
#define TF_R(d) { x0 += x1; x1 = __funnelshift_l(x1, x1, d); x1 ^= x0; }

template<unsigned K0, unsigned K1>
__device__ __forceinline__ KP tf_block_dev(unsigned x0, unsigned x1) {
  constexpr unsigned K2 = K0 ^ K1 ^ 0x1BD11BDAu;
  x0 += K0; x1 += K1;
  TF_R(13) TF_R(15) TF_R(26) TF_R(6)    x0 += K1; x1 += K2 + 1u;
  TF_R(17) TF_R(29) TF_R(16) TF_R(24)   x0 += K2; x1 += K0 + 2u;
  TF_R(13) TF_R(15) TF_R(26) TF_R(6)    x0 += K0; x1 += K1 + 3u;
  TF_R(17) TF_R(29) TF_R(16) TF_R(24)   x0 += K1; x1 += K2 + 4u;
  TF_R(13) TF_R(15) TF_R(26) TF_R(6)    x0 += K2; x1 += K0 + 5u;
  KP r; r.a = x0; r.b = x1; return r;
}

// One 32-bit draw for flat mask element i. keep <=> (draw >> 31) == 0.
template<unsigned K0, unsigned K1>
__device__ __forceinline__ unsigned rng_draw(unsigned i) {
#if JAX_PARTITIONABLE
  KP o = tf_block_dev<K0, K1>(0u, i);
#if PART_XOR
  return o.a ^ o.b;
#else
  return o.a;
#endif
#else
  if (i < (unsigned)MASK_HALF) {        // uniform per block (m fixed per block)
    KP o = tf_block_dev<K0, K1>(i, i + (unsigned)MASK_HALF);
    return o.a;
  } else {
    KP o = tf_block_dev<K0, K1>(i - (unsigned)MASK_HALF, i);
    return o.b;
  }
#endif
}

__device__ __forceinline__ float tanh_fast(float x) {
  float y;
  asm("tanh.approx.f32 %0, %1;" : "=f"(y) : "f"(x));
  return y;
}

// ---------------------------------------------------------------------------
// Prologue: t1[n,f] = tanh(2 * input[n] * W1[f])  (accurate tanhf; only 131K)
// ---------------------------------------------------------------------------
__device__ float g_t1[SEQ * NF];

__global__ void t1_kernel(const float* __restrict__ input,
                          const float* __restrict__ W1) {
  int i = blockIdx.x * blockDim.x + threadIdx.x;   // over SEQ*NF
  int n = i >> 6, f = i & 63;
  g_t1[i] = tanhf(2.0f * input[n] * W1[f]);
}

// ---------------------------------------------------------------------------
// Main fused kernel. Block: 128 n-lanes x MPB m-samples.
// Static smem: W2 16KB + t1 slab (transposed, conflict-free) 32KB = 48KB exact.
// ---------------------------------------------------------------------------
__global__ void __launch_bounds__(TB, 4)
mc_kernel(const float* __restrict__ W2,
          const float* __restrict__ Wf,
          float* __restrict__ out) {
  __shared__ __align__(16) float sW2[NF * NF];     // [g][f], row-contiguous
  __shared__ __align__(16) float sT1[NF * TB];     // [f][n_local] (transposed)

  const int tid = threadIdx.x;
  const int n0  = blockIdx.x * TB;
  const int m0  = blockIdx.y * MPB;
  const int n   = n0 + tid;

  // W2 -> shared, vectorized, coalesced
  {
    const float4* src = reinterpret_cast<const float4*>(W2);
    float4* dst = reinterpret_cast<float4*>(sW2);
#pragma unroll 1
    for (int i = tid; i < NF * NF / 4; i += TB) dst[i] = src[i];
  }
  // t1 slab -> shared transposed: sT1[f*TB + n_local]; lane reads its own row
  // (sequential per lane, L1-assembled), LDS stores conflict-free.
#pragma unroll 1
  for (int f = 0; f < NF; ++f)
    sT1[f * TB + tid] = g_t1[(n0 + tid) * NF + f];
  __syncthreads();

#pragma unroll 1
  for (int mi = 0; mi < MPB; ++mi) {
    const unsigned m = (unsigned)(m0 + mi);
    const unsigned base = (m * SEQ + (unsigned)n) * NF;

    // ---- layer 1: draw 64 mask1 bits, build masked t1 row in registers ----
    float x1v[NF];
#pragma unroll
    for (int f = 0; f < NF; ++f) {
      unsigned r = rng_draw<KM1.a, KM1.b>(base + (unsigned)f);
      x1v[f] = (r & 0x80000000u) ? 0.0f : sT1[f * TB + tid];
    }

    // ---- layer 2 + readout: per output feature g ----
    float oacc = 0.0f;
#pragma unroll 2
    for (int g = 0; g < NF; ++g) {
      const float4* row = reinterpret_cast<const float4*>(sW2 + g * NF);
      float a0 = 0.f, a1 = 0.f, a2 = 0.f, a3 = 0.f;
#pragma unroll
      for (int q = 0; q < NF / 4; ++q) {
        float4 w = row[q];                 // LDS.128 broadcast
        a0 = fmaf(x1v[4 * q + 0], w.x, a0);
        a1 = fmaf(x1v[4 * q + 1], w.y, a1);
        a2 = fmaf(x1v[4 * q + 2], w.z, a2);
        a3 = fmaf(x1v[4 * q + 3], w.w, a3);
      }
      float x2 = (a0 + a1) + (a2 + a3);
      unsigned r2 = rng_draw<KM2.a, KM2.b>(base + (unsigned)g);
      float t = tanh_fast(2.0f * x2);
      float y = (r2 & 0x80000000u) ? 0.0f : t;
      oacc = fmaf(y, __ldg(&Wf[g]), oacc);
    }
    out[m * SEQ + (unsigned)n] = oacc;
  }
}

// ---------------------------------------------------------------------------
extern "C" void kernel_launch(void* const* d_in, const int* in_sizes, int n_in,
                              void* d_out, int out_size) {
  const float* input = (const float*)d_in[0];   // [2048,1]
  const float* W1    = (const float*)d_in[1];   // [64,1]
  const float* W2    = (const float*)d_in[2];   // [64,64]
  const float* Wf    = (const float*)d_in[3];   // [1,64]
  float* out         = (float*)d_out;           // [1024,2048,1]

  t1_kernel<<<(SEQ * NF) / 256, 256>>>(input, W1);
  mc_kernel<<<dim3(SEQ / TB, NMC / MPB), TB>>>(W2, Wf, out);
}

// round 3
// speedup vs baseline: 1.0291x; 1.0291x over previous
#include <cuda_runtime.h>
#include <cuda_fp16.h>
#include <cstdint>

// ============================================================================
// MonteCarloNet: out[m,n] = sum_g Wf[g] * tanh(2*mask2[m,n,g] *
//                  sum_f (mask1[m,n,f]*tanh(2*in[n]*W1[f])) * W2[g,f])
// Masks: bit-exact JAX threefry2x32 (partitionable mode, CONFIRMED R1:
// rel_err 4.3e-6), key(42) -> km1, km2; draw_i = block(km,0,i).o0 ^ .o1;
// keep <=> MSB==0.
// ============================================================================

#define NMC   1024
#define SEQ   2048
#define NF    64
#define TB    128            // threads per block (over n)
#define MPB   8              // m samples per block

struct KP { unsigned a, b; };

__host__ __device__ constexpr unsigned rotl32c(unsigned x, int d) {
  return (x << d) | (x >> (32 - d));
}

// Reference threefry2x32 block (constexpr for the key schedule).
__host__ __device__ constexpr KP tf_block_c(unsigned k0, unsigned k1,
                                            unsigned x0, unsigned x1) {
  unsigned ks[3] = {k0, k1, k0 ^ k1 ^ 0x1BD11BDAu};
  int rot[2][4] = {{13, 15, 26, 6}, {17, 29, 16, 24}};
  x0 += ks[0]; x1 += ks[1];
  for (int g = 0; g < 5; ++g) {
    for (int j = 0; j < 4; ++j) {
      x0 += x1;
      x1 = rotl32c(x1, rot[g & 1][j]);
      x1 ^= x0;
    }
    x0 += ks[(g + 1) % 3];
    x1 += ks[(g + 2) % 3] + (unsigned)(g + 1);
  }
  return {x0, x1};
}

constexpr KP KM1 = tf_block_c(0u, 42u, 0u, 0u);
constexpr KP KM2 = tf_block_c(0u, 42u, 0u, 1u);

#define TF_R(d) { x0 += x1; x1 = __funnelshift_l(x1, x1, d); x1 ^= x0; }

template<unsigned K0, unsigned K1>
__device__ __forceinline__ unsigned rng_draw(unsigned i) {
  constexpr unsigned K2 = K0 ^ K1 ^ 0x1BD11BDAu;
  unsigned x0 = K0, x1 = i + K1;
  TF_R(13) TF_R(15) TF_R(26) TF_R(6)    x0 += K1; x1 += K2 + 1u;
  TF_R(17) TF_R(29) TF_R(16) TF_R(24)   x0 += K2; x1 += K0 + 2u;
  TF_R(13) TF_R(15) TF_R(26) TF_R(6)    x0 += K0; x1 += K1 + 3u;
  TF_R(17) TF_R(29) TF_R(16) TF_R(24)   x0 += K1; x1 += K2 + 4u;
  TF_R(13) TF_R(15) TF_R(26) TF_R(6)    x0 += K2; x1 += K0 + 5u;
  return x0 ^ x1;
}

// keep <=> MSB(r)==0. Branch-free: v & ~(sign-extend(r)). 2 alu ops, no pred.
__device__ __forceinline__ float mask_apply(float v, unsigned r) {
  unsigned km = ~(unsigned)((int)r >> 31);
  return __uint_as_float(__float_as_uint(v) & km);
}

__device__ __forceinline__ float tanh_fast(float x) {
  float y;
  asm("tanh.approx.f32 %0, %1;" : "=f"(y) : "f"(x));
  return y;
}

// ---------------------------------------------------------------------------
// Prologue: t1T[f*SEQ + n] = tanh(2*in[n]*W1[f]) as fp16, TRANSPOSED so the
// main kernel's slab load is coalesced. (accurate tanhf; only 131K elements)
// ---------------------------------------------------------------------------
__device__ __half g_t1T[NF * SEQ];

__global__ void t1_kernel(const float* __restrict__ input,
                          const float* __restrict__ W1) {
  int i = blockIdx.x * blockDim.x + threadIdx.x;   // i = f*SEQ + n
  int f = i >> 11, n = i & (SEQ - 1);
  g_t1T[i] = __float2half(tanhf(2.0f * input[n] * W1[f]));
}

// ---------------------------------------------------------------------------
// Main fused kernel. Block: 128 n-lanes x MPB m-samples.
// smem: W2 (pre-doubled) 16KB + t1 slab fp16 16KB + Wf 256B ~= 32.5KB.
// launch_bounds(128,5): <=102 regs -> 5 blocks = 20 warps/SM.
// ---------------------------------------------------------------------------
__global__ void __launch_bounds__(TB, 5)
mc_kernel(const float* __restrict__ W2,
          const float* __restrict__ Wf,
          float* __restrict__ out) {
  __shared__ __align__(16) float  sW2[NF * NF];    // [g][f], pre-multiplied by 2
  __shared__ __align__(16) __half sT1[NF * TB];    // [f][n_local]
  __shared__ __align__(16) float  sWf[NF];

  const int tid = threadIdx.x;
  const int n0  = blockIdx.x * TB;
  const int m0  = blockIdx.y * MPB;
  const int n   = n0 + tid;

  // W2 -> shared, pre-doubled (folds the KEEP_SCALE=2 of dropout layer 2)
  {
    const float4* src = reinterpret_cast<const float4*>(W2);
    float4* dst = reinterpret_cast<float4*>(sW2);
#pragma unroll 1
    for (int i = tid; i < NF * NF / 4; i += TB) {
      float4 v = src[i];
      v.x *= 2.0f; v.y *= 2.0f; v.z *= 2.0f; v.w *= 2.0f;
      dst[i] = v;
    }
  }
  if (tid < NF) sWf[tid] = Wf[tid];
  // t1 slab -> shared (coalesced: g_t1T is [f][n])
#pragma unroll 1
  for (int f = 0; f < NF; ++f)
    sT1[f * TB + tid] = g_t1T[f * SEQ + n0 + tid];
  __syncthreads();

#pragma unroll 1
  for (int mi = 0; mi < MPB; ++mi) {
    const unsigned m = (unsigned)(m0 + mi);
    const unsigned base = (m * SEQ + (unsigned)n) * NF;

    // ---- layer 1: draw 64 mask1 bits, masked t1 row in registers ----
    float x1v[NF];
#pragma unroll
    for (int f = 0; f < NF; ++f) {
      unsigned r = rng_draw<KM1.a, KM1.b>(base + (unsigned)f);
      x1v[f] = mask_apply(__half2float(sT1[f * TB + tid]), r);
    }

    // ---- layer 2 + readout ----
    float oacc = 0.0f;
#pragma unroll 2
    for (int g = 0; g < NF; ++g) {
      const float4* row = reinterpret_cast<const float4*>(sW2 + g * NF);
      float a0 = 0.f, a1 = 0.f, a2 = 0.f, a3 = 0.f;
#pragma unroll
      for (int q = 0; q < NF / 4; ++q) {
        float4 w = row[q];                 // LDS.128 broadcast
        a0 = fmaf(x1v[4 * q + 0], w.x, a0);
        a1 = fmaf(x1v[4 * q + 1], w.y, a1);
        a2 = fmaf(x1v[4 * q + 2], w.z, a2);
        a3 = fmaf(x1v[4 * q + 3], w.w, a3);
      }
      float x2 = (a0 + a1) + (a2 + a3);    // already includes the *2
      unsigned r2 = rng_draw<KM2.a, KM2.b>(base + (unsigned)g);
      float y = mask_apply(tanh_fast(x2), r2);
      oacc = fmaf(y, sWf[g], oacc);
    }
    out[m * SEQ + (unsigned)n] = oacc;
  }
}

// ---------------------------------------------------------------------------
extern "C" void kernel_launch(void* const* d_in, const int* in_sizes, int n_in,
                              void* d_out, int out_size) {
  const float* input = (const float*)d_in[0];   // [2048,1]
  const float* W1    = (const float*)d_in[1];   // [64,1]
  const float* W2    = (const float*)d_in[2];   // [64,64]
  const float* Wf    = (const float*)d_in[3];   // [1,64]
  float* out         = (float*)d_out;           // [1024,2048,1]

  t1_kernel<<<(SEQ * NF) / 256, 256>>>(input, W1);
  mc_kernel<<<dim3(SEQ / TB, NMC / MPB), TB>>>(W2, Wf, out);
}

// round 7
// speedup vs baseline: 1.0982x; 1.0671x over previous
#include <cuda_runtime.h>
#include <cuda_fp16.h>
#include <cstdint>

// ============================================================================
// MonteCarloNet: out[m,n] = sum_g Wf[g] * tanh(mask2 * 2 * sum_f
//                  (mask1 * t1[n,f]) * W2[g,f]),  t1[n,f]=tanh(2 in[n] W1[f])
// (keep-scales folded: layer-1 scale into t1 arg, layer-2 x2 into W2.)
// Masks: bit-exact JAX threefry2x32 partitionable (CONFIRMED R1, rel 4.3e-6),
// key(42); draw_i = block(km,0,i).o0 ^ .o1 ; keep <=> MSB==0.
// Matvec: packed fma.rn.f32x2 (2 fp32 MACs/instr). R5/R6 failed with an
// identical rel_err because the q-loop covered only HALF the row (q<8 over
// 16B ulonglong2 = 32 floats). Fixed: q<16 covers all 64 floats.
// ============================================================================

#define NMC   1024
#define SEQ   2048
#define NF    64
#define TB    128            // threads per block (over n)
#define MPB   8              // m samples per block

typedef unsigned long long ull;

union PackF2 { ull u; float2 f; unsigned w[2]; };

struct KP { unsigned a, b; };

__host__ __device__ constexpr unsigned rotl32c(unsigned x, int d) {
  return (x << d) | (x >> (32 - d));
}
__host__ __device__ constexpr KP tf_block_c(unsigned k0, unsigned k1,
                                            unsigned x0, unsigned x1) {
  unsigned ks[3] = {k0, k1, k0 ^ k1 ^ 0x1BD11BDAu};
  int rot[2][4] = {{13, 15, 26, 6}, {17, 29, 16, 24}};
  x0 += ks[0]; x1 += ks[1];
  for (int g = 0; g < 5; ++g) {
    for (int j = 0; j < 4; ++j) {
      x0 += x1; x1 = rotl32c(x1, rot[g & 1][j]); x1 ^= x0;
    }
    x0 += ks[(g + 1) % 3];
    x1 += ks[(g + 2) % 3] + (unsigned)(g + 1);
  }
  return {x0, x1};
}
constexpr KP KM1 = tf_block_c(0u, 42u, 0u, 0u);
constexpr KP KM2 = tf_block_c(0u, 42u, 0u, 1u);

#define TF_R(d) { x0 += x1; x1 = __funnelshift_l(x1, x1, d); x1 ^= x0; }

template<unsigned K0, unsigned K1>
__device__ __forceinline__ unsigned rng_draw(unsigned i) {
  constexpr unsigned K2 = K0 ^ K1 ^ 0x1BD11BDAu;
  unsigned x0 = K0, x1 = i + K1;
  TF_R(13) TF_R(15) TF_R(26) TF_R(6)    x0 += K1; x1 += K2 + 1u;
  TF_R(17) TF_R(29) TF_R(16) TF_R(24)   x0 += K2; x1 += K0 + 2u;
  TF_R(13) TF_R(15) TF_R(26) TF_R(6)    x0 += K0; x1 += K1 + 3u;
  TF_R(17) TF_R(29) TF_R(16) TF_R(24)   x0 += K1; x1 += K2 + 4u;
  TF_R(13) TF_R(15) TF_R(26) TF_R(6)    x0 += K2; x1 += K0 + 5u;
  return x0 ^ x1;
}

// keep <=> MSB(r)==0. Branch-free AND masking (tanh(0)=0 makes this exact).
__device__ __forceinline__ float mask_apply(float v, unsigned r) {
  unsigned km = ~(unsigned)((int)r >> 31);
  return __uint_as_float(__float_as_uint(v) & km);
}
__device__ __forceinline__ float tanh_fast(float x) {
  float y; asm("tanh.approx.f32 %0, %1;" : "=f"(y) : "f"(x)); return y;
}

// ---- packed f32x2 arithmetic (base sm_100 ISA; operands are plain b64) ----
__device__ __forceinline__ void ffma2(ull& d, ull a, ull b) {
  asm("fma.rn.f32x2 %0, %1, %2, %0;" : "+l"(d) : "l"(a), "l"(b));
}
__device__ __forceinline__ ull addf2(ull a, ull b) {
  ull d; asm("add.rn.f32x2 %0, %1, %2;" : "=l"(d) : "l"(a), "l"(b));
  return d;
}

// ---------------------------------------------------------------------------
// Prologue: packed t1 pairs, transposed:
//   g_t1p[fp*SEQ + n] = half2( t1[n,2fp], t1[n,2fp+1] )
// ---------------------------------------------------------------------------
__device__ unsigned g_t1p[(NF / 2) * SEQ];

__global__ void t1_kernel(const float* __restrict__ input,
                          const float* __restrict__ W1) {
  int i = blockIdx.x * blockDim.x + threadIdx.x;   // over 32*2048
  int fp = i >> 11, n = i & (SEQ - 1);
  float x = 2.0f * input[n];
  __half2 h = __floats2half2_rn(tanhf(x * W1[2 * fp]), tanhf(x * W1[2 * fp + 1]));
  g_t1p[i] = *reinterpret_cast<unsigned*>(&h);
}

// ---------------------------------------------------------------------------
// Main fused kernel. 128 n-lanes x MPB m-samples per block.
// smem: W2 fp32 pre-doubled 16KB + t1 half2 slab 16KB + Wf 256B ~= 32.5KB.
// ---------------------------------------------------------------------------
__global__ void __launch_bounds__(TB, 5)
mc_kernel(const float* __restrict__ W2,
          const float* __restrict__ Wf,
          float* __restrict__ out) {
  __shared__ __align__(16) float    sW2[NF * NF];       // [g][f], x2 pre-folded
  __shared__ __align__(16) unsigned sT1[(NF / 2) * TB]; // [fp][n_local] half2
  __shared__ __align__(16) float    sWf[NF];

  const int tid = threadIdx.x;
  const int n0  = blockIdx.x * TB;
  const int m0  = blockIdx.y * MPB;
  const int n   = n0 + tid;

  // W2 -> shared fp32, pre-doubled
  {
    const float4* src = reinterpret_cast<const float4*>(W2);
    float4* dst = reinterpret_cast<float4*>(sW2);
#pragma unroll 1
    for (int i = tid; i < NF * NF / 4; i += TB) {
      float4 v = src[i];
      v.x *= 2.0f; v.y *= 2.0f; v.z *= 2.0f; v.w *= 2.0f;
      dst[i] = v;
    }
  }
  if (tid < NF) sWf[tid] = Wf[tid];
  // t1 half2 slab -> shared (coalesced: g_t1p is [fp][n])
#pragma unroll 1
  for (int fp = 0; fp < NF / 2; ++fp)
    sT1[fp * TB + tid] = g_t1p[fp * SEQ + n0 + tid];
  __syncthreads();

#pragma unroll 1
  for (int mi = 0; mi < MPB; ++mi) {
    const unsigned m = (unsigned)(m0 + mi);
    const unsigned base = (m * SEQ + (unsigned)n) * NF;

    // ---- phase 1: 64 mask1 draws -> masked x1 as 32 packed f32x2 regs ----
    // Union-based pack: float2.x <-> low 32 bits of .u, guaranteed by layout.
    ull x1p[NF / 2];
#pragma unroll
    for (int fp = 0; fp < NF / 2; ++fp) {
      unsigned hp = sT1[fp * TB + tid];
      PackF2 cv;
      cv.f = __half22float2(*reinterpret_cast<__half2*>(&hp));
      unsigned r0 = rng_draw<KM1.a, KM1.b>(base + 2 * fp);
      unsigned r1 = rng_draw<KM1.a, KM1.b>(base + 2 * fp + 1);
      cv.w[0] &= ~(unsigned)((int)r0 >> 31);   // element 2fp   (low word)
      cv.w[1] &= ~(unsigned)((int)r1 >> 31);   // element 2fp+1 (high word)
      x1p[fp] = cv.u;
    }

    // ---- phase 2: layer 2 (packed f32x2 matvec) + mask2 + readout ----
    float oacc = 0.0f;
#pragma unroll 2
    for (int g = 0; g < NF; ++g) {
      // W2 row as 64-bit words straight from shared memory: low address ->
      // low bits (little endian), pairing elements (2q, 2q+1) per word.
      const ulonglong2* row = reinterpret_cast<const ulonglong2*>(sW2 + g * NF);
      ull a0 = 0, a1 = 0, a2 = 0, a3 = 0;
#pragma unroll
      for (int q = 0; q < 16; ++q) {       // 16 x ulonglong2 = 64 floats (FIX)
        ulonglong2 w = row[q];             // w.x = f(4q,4q+1), w.y = f(4q+2,4q+3)
        if (q & 1) {
          ffma2(a2, x1p[2 * q + 0], w.x);
          ffma2(a3, x1p[2 * q + 1], w.y);
        } else {
          ffma2(a0, x1p[2 * q + 0], w.x);
          ffma2(a1, x1p[2 * q + 1], w.y);
        }
      }
      PackF2 s; s.u = addf2(addf2(a0, a1), addf2(a2, a3));
      float x2 = s.f.x + s.f.y;            // x2 already includes the *2
      unsigned r2 = rng_draw<KM2.a, KM2.b>(base + (unsigned)g);
      float y = mask_apply(tanh_fast(x2), r2);
      oacc = fmaf(y, sWf[g], oacc);
    }
    out[m * SEQ + (unsigned)n] = oacc;
  }
}

// ---------------------------------------------------------------------------
extern "C" void kernel_launch(void* const* d_in, const int* in_sizes, int n_in,
                              void* d_out, int out_size) {
  const float* input = (const float*)d_in[0];   // [2048,1]
  const float* W1    = (const float*)d_in[1];   // [64,1]
  const float* W2    = (const float*)d_in[2];   // [64,64]
  const float* Wf    = (const float*)d_in[3];   // [1,64]
  float* out         = (float*)d_out;           // [1024,2048,1]

  t1_kernel<<<((NF / 2) * SEQ) / 256, 256>>>(input, W1);
  mc_kernel<<<dim3(SEQ / TB, NMC / MPB), TB>>>(W2, Wf, out);
}